// round 17
// baseline (speedup 1.0000x reference)
#include <cuda_runtime.h>
#include <cuda_bf16.h>
#include <math.h>
#include <stdint.h>

// ---------------- problem constants (static per reference) ----------------
#define BSZ   8
#define NQ    4096
#define CDIM  256
#define NHEAD 8
#define NPT   4
#define NLVL  6
#define NVAL  10752
#define DHEAD 32
#define NOFF  384
#define NATT  192
#define NQA   576
#define NWT   1088
#define MQ    (BSZ * NQ)   // 32768
#define MV    (BSZ * NVAL) // 86016
#define NSLC  4
#define MVS   (MV / NSLC)  // 21504
#define MQS   (MQ / NSLC)  // 8192

// ---------------- device scratch (static, no allocation) ------------------
__device__ __nv_bfloat16 g_vbf [(size_t)MV * CDIM];    // vproj bf16, head-major
__device__ float g_qa   [(size_t)MQ * NQA];            // [off(384) | attn(192)]
__device__ __nv_bfloat16 g_val_h[(size_t)MV * CDIM];   // value bf16 (hi only)
__device__ __nv_bfloat16 g_q_h  [(size_t)MQ * CDIM];
__device__ __nv_bfloat16 g_q_l  [(size_t)MQ * CDIM];
__device__ __nv_bfloat16 g_ms_h [(size_t)MQ * CDIM];   // deform-attn out (bf16)
__device__ __nv_bfloat16 g_Wt_hi[NWT * CDIM];
__device__ __nv_bfloat16 g_Wt_lo[NWT * CDIM];
__device__ float g_bias[NWT];

__constant__ int c_H[NLVL] = {64, 32, 16, 64, 32, 16};
__constant__ int c_W[NLVL] = {64, 32, 16, 64, 32, 16};
__constant__ int c_S[NLVL] = {0, 4096, 5120, 5376, 9472, 10496};

// ---------------- small helpers -------------------------------------------
__device__ __forceinline__ uint32_t smem_u32(const void* p) {
    uint32_t a;
    asm("{ .reg .u64 t; cvta.to.shared.u64 t, %1; cvt.u32.u64 %0, t; }"
        : "=r"(a) : "l"(p));
    return a;
}
__device__ __forceinline__ void ldsm_x4(uint32_t* r, uint32_t addr) {
    asm volatile("ldmatrix.sync.aligned.m8n8.x4.shared.b16 {%0,%1,%2,%3}, [%4];"
                 : "=r"(r[0]), "=r"(r[1]), "=r"(r[2]), "=r"(r[3]) : "r"(addr));
}
__device__ __forceinline__ void ldsm_x4t(uint32_t* r, uint32_t addr) {
    asm volatile("ldmatrix.sync.aligned.m8n8.x4.trans.shared.b16 {%0,%1,%2,%3}, [%4];"
                 : "=r"(r[0]), "=r"(r[1]), "=r"(r[2]), "=r"(r[3]) : "r"(addr));
}
__device__ __forceinline__ void mma_bf16(float* c, const uint32_t* a,
                                         const uint32_t* b) {
    asm volatile(
        "mma.sync.aligned.m16n8k16.row.col.f32.bf16.bf16.f32 "
        "{%0,%1,%2,%3}, {%4,%5,%6,%7}, {%8,%9}, {%0,%1,%2,%3};"
        : "+f"(c[0]), "+f"(c[1]), "+f"(c[2]), "+f"(c[3])
        : "r"(a[0]), "r"(a[1]), "r"(a[2]), "r"(a[3]), "r"(b[0]), "r"(b[1]));
}
__device__ __forceinline__ uint32_t pack_bf16(float x, float y) {
    __nv_bfloat162 t = __halves2bfloat162(__float2bfloat16_rn(x),
                                          __float2bfloat16_rn(y));
    return *(uint32_t*)&t;
}
__device__ __forceinline__ void cp16(uint32_t dst, const void* src) {
    asm volatile("cp.async.cg.shared.global [%0], [%1], 16;"
                 :: "r"(dst), "l"(src));
}
__device__ __forceinline__ void cp16ca(uint32_t dst, const void* src) {
    asm volatile("cp.async.ca.shared.global [%0], [%1], 16;"
                 :: "r"(dst), "l"(src));
}
#define CP_COMMIT() asm volatile("cp.async.commit_group;" ::: "memory")
#define CP_WAIT(n)  asm volatile("cp.async.wait_group %0;" :: "n"(n) : "memory")

// ============== prep branch A: W_off/attn/out + q split =====================
#define PQW_B0 832
#define PQW_NB (PQW_B0 + (MQ * CDIM / 4) / 256)     // 832 + 8192

__global__ __launch_bounds__(256)
void prep_qw_kernel(const float* __restrict__ W_off,
                    const float* __restrict__ b_off,
                    const float* __restrict__ W_attn,
                    const float* __restrict__ b_attn,
                    const float* __restrict__ W_out,
                    const float* __restrict__ b_out,
                    const float* __restrict__ query,
                    const float* __restrict__ qpos)
{
    const int bx = blockIdx.x;
    const int tid = threadIdx.x;
    if (bx < PQW_B0) {
        const int n = bx + 256, k = tid;   // rows 256..1087
        const int m = n - 256;
        float x, bb;
        if (m < 384)      { x = W_off[k * 384 + m];          bb = b_off[m]; }
        else if (m < 576) { x = W_attn[k * 192 + (m - 384)]; bb = b_attn[m - 384]; }
        else              { x = W_out[k * 256 + (m - 576)];  bb = b_out[m - 576]; }
        const __nv_bfloat16 hi = __float2bfloat16_rn(x);
        const __nv_bfloat16 lo = __float2bfloat16_rn(x - __bfloat162float(hi));
        g_Wt_hi[n * CDIM + k] = hi;
        g_Wt_lo[n * CDIM + k] = lo;
        if (k == 0) g_bias[n] = bb;
        return;
    }
    const size_t i4 = (size_t)(bx - PQW_B0) * 256 + tid;
    float4 v = ((const float4*)query)[i4];
    const float4 u = ((const float4*)qpos)[i4];
    v.x += u.x; v.y += u.y; v.z += u.z; v.w += u.w;
    const float hx = __bfloat162float(__float2bfloat16_rn(v.x));
    const float hy = __bfloat162float(__float2bfloat16_rn(v.y));
    const float hz = __bfloat162float(__float2bfloat16_rn(v.z));
    const float hw = __bfloat162float(__float2bfloat16_rn(v.w));
    ((uint2*)g_q_h)[i4] = make_uint2(pack_bf16(v.x, v.y), pack_bf16(v.z, v.w));
    ((uint2*)g_q_l)[i4] = make_uint2(pack_bf16(v.x - hx, v.y - hy),
                                     pack_bf16(v.z - hz, v.w - hw));
}

// ============== prep branch B: W_val (hi) + value -> bf16 ===================
#define PV_B0 256
#define PV_NB (PV_B0 + (MV * CDIM / 4) / 256)       // 256 + 21504

__global__ __launch_bounds__(256)
void prep_v_kernel(const float* __restrict__ value,
                   const float* __restrict__ W_val,
                   const float* __restrict__ b_val)
{
    const int bx = blockIdx.x;
    const int tid = threadIdx.x;
    if (bx < PV_B0) {
        const int n = bx, k = tid;
        g_Wt_hi[n * CDIM + k] = __float2bfloat16_rn(W_val[k * 256 + n]);
        if (k == 0) g_bias[n] = b_val[n];
        return;
    }
    const size_t i4 = (size_t)(bx - PV_B0) * 256 + tid;
    const float4 v = ((const float4*)value)[i4];
    ((uint2*)g_val_h)[i4] = make_uint2(pack_bf16(v.x, v.y), pack_bf16(v.z, v.w));
}

// ============== bf16-split HMMA GEMM, 2-stage dual-sync =====================
// MODE 0 (qa):    3 terms; MODE 1 (out): 2 terms + resid; MODE 2 (vproj): 1 term
#define HG_STG   24576
#define HG_SMEM  49152

template <int MODE>
__global__ __launch_bounds__(256, 4)
void hgemm2_kernel(const __nv_bfloat16* __restrict__ Ath,
                   const __nv_bfloat16* __restrict__ Atl,
                   const __nv_bfloat16* __restrict__ Bth,
                   const __nv_bfloat16* __restrict__ Btl,
                   const float* __restrict__ bias,
                   const float* __restrict__ resid, float* __restrict__ Cf,
                   __nv_bfloat16* __restrict__ Cb,
                   int m0, int N, int K)
{
    constexpr bool A_LO = (MODE == 0);
    constexpr bool B_LO = (MODE != 2);

    extern __shared__ __align__(16) uint8_t smem[];
    const uint32_t uS = smem_u32(smem);

    const int tid  = threadIdx.x;
    const int lane = tid & 31;
    const int wid  = tid >> 5;
    const int wm   = wid >> 1;
    const int wn   = wid & 1;
    const int bm   = m0 + blockIdx.x * 128;
    const int bn   = blockIdx.y * 64;
    const int KT   = K >> 5;

    const int lrA  = ((lane >> 3) & 1) * 8 + (lane & 7);
    const int lk8A = lane >> 4;
    const int rowA = wm * 32 + lrA;
    const int xrA  = (rowA >> 1) & 3;
    const uint32_t offA0 = (uint32_t)(rowA * 64 + ((0 * 2 + lk8A) ^ xrA) * 16);
    const uint32_t offA1 = (uint32_t)(rowA * 64 + ((1 * 2 + lk8A) ^ xrA) * 16);

    const int lrB  = (lane >> 4) * 8 + (lane & 7);
    const int lk8B = (lane >> 3) & 1;
    const int rowB = wn * 32 + lrB;
    const int xrB  = (rowB >> 1) & 3;
    const uint32_t offB0 = (uint32_t)(16384 + rowB * 64 + ((0 * 2 + lk8B) ^ xrB) * 16);
    const uint32_t offB1 = (uint32_t)(16384 + rowB * 64 + ((1 * 2 + lk8B) ^ xrB) * 16);

    const int ar0 = tid >> 2, ac0 = tid & 3;
    const int ar1 = ar0 + 64;
    const int br  = tid >> 2, bc = tid & 3;
    const uint32_t sA0 = (uint32_t)(ar0 * 64 + ((ac0 ^ ((ar0 >> 1) & 3)) * 16));
    const uint32_t sA1 = (uint32_t)(ar1 * 64 + ((ac0 ^ ((ar1 >> 1) & 3)) * 16));
    const uint32_t sB  = (uint32_t)(16384 + br * 64 + ((bc ^ ((br >> 1) & 3)) * 16));

    float acc[2][4][4];
#pragma unroll
    for (int t = 0; t < 2; t++)
#pragma unroll
        for (int u = 0; u < 4; u++)
#pragma unroll
            for (int i = 0; i < 4; i++) acc[t][u][i] = 0.f;

    auto issue = [&](int kt, int buf) {
        const int k0 = kt * 32;
        const uint32_t base = uS + buf * HG_STG;
        const size_t oa0 = (size_t)(bm + ar0) * K + k0 + ac0 * 8;
        const size_t oa1 = (size_t)(bm + ar1) * K + k0 + ac0 * 8;
        const size_t ob  = (size_t)(bn + br ) * K + k0 + bc  * 8;
        cp16(base +         sA0, Ath + oa0);
        cp16(base +         sA1, Ath + oa1);
        if (A_LO) {
            cp16(base + 8192u + sA0, Atl + oa0);
            cp16(base + 8192u + sA1, Atl + oa1);
        }
        cp16(base +         sB,  Bth + ob);
        if (B_LO)
            cp16(base + 4096u + sB, Btl + ob);
        CP_COMMIT();
    };

    issue(0, 0);
    issue(1, 1);

#pragma unroll 1
    for (int kt = 0; kt < KT; kt++) {
        if (kt == KT - 1) { CP_WAIT(0); } else { CP_WAIT(1); }
        __syncthreads();

        const uint32_t sb = uS + (kt & 1) * HG_STG;
#pragma unroll
        for (int ks = 0; ks < 2; ks++) {
            const uint32_t oA = sb + (ks ? offA1 : offA0);
            const uint32_t oB = sb + (ks ? offB1 : offB0);
            uint32_t bH[4][2], bL[4][2];
            ldsm_x4(&bH[0][0], oB);
            ldsm_x4(&bH[2][0], oB + 1024);
            if (B_LO) {
                ldsm_x4(&bL[0][0], oB + 4096);
                ldsm_x4(&bL[2][0], oB + 4096 + 1024);
            }
#pragma unroll
            for (int t = 0; t < 2; t++) {
                uint32_t aH[4], aL[4];
                ldsm_x4(aH, oA + t * 1024);
                if (A_LO) ldsm_x4(aL, oA + 8192 + t * 1024);
#pragma unroll
                for (int u = 0; u < 4; u++) {
                    mma_bf16(acc[t][u], aH, bH[u]);
                    if (B_LO) mma_bf16(acc[t][u], aH, bL[u]);
                    if (A_LO) mma_bf16(acc[t][u], aL, bH[u]);
                }
            }
        }
        __syncthreads();
        if (kt + 2 < KT) issue(kt + 2, kt & 1);
    }

    // ---- epilogue ----
    const int g = lane >> 2, tg = lane & 3;
    const int batch = bm / NVAL;
    const int head  = (bn + wn * 32) >> 5;
#pragma unroll
    for (int t = 0; t < 2; t++)
#pragma unroll
        for (int u = 0; u < 4; u++) {
            const int row = bm + wm * 32 + t * 16 + g;
            const int col = bn + wn * 32 + u * 8 + tg * 2;
            const float2 bv = *(const float2*)(bias + col);
            float2 o0 = make_float2(acc[t][u][0] + bv.x, acc[t][u][1] + bv.y);
            float2 o1 = make_float2(acc[t][u][2] + bv.x, acc[t][u][3] + bv.y);
            if (MODE == 1) {
                const float2 r0 = *(const float2*)(resid + (size_t)row * N + col);
                const float2 r1 = *(const float2*)(resid + (size_t)(row + 8) * N + col);
                o0.x += r0.x; o0.y += r0.y;
                o1.x += r1.x; o1.y += r1.y;
            }
            if (MODE == 2) {
                const int nv = row - batch * NVAL;
                const int dim = u * 8 + tg * 2;
                const size_t base =
                    ((size_t)(batch * NHEAD + head) * NVAL + nv) * DHEAD + dim;
                *(uint32_t*)(Cb + base)              = pack_bf16(o0.x, o0.y);
                *(uint32_t*)(Cb + base + 8 * DHEAD)  = pack_bf16(o1.x, o1.y);
            } else {
                *(float2*)(Cf + (size_t)row * N + col) = o0;
                *(float2*)(Cf + (size_t)(row + 8) * N + col) = o1;
            }
        }
}

// ---------------- sampling kernel: tensor-core weighted gather --------------
// Per warp (bq,h): ms[32] = w[96] . V[96][32].
// Phase 1: lanes 0..23 softmax + 4 corner (offset, bf16 weight) -> smem.
// Phase 2: cp.async.ca gathers 96 x 64B V rows into a swizzled smem tile.
// Phase 3: A = V^T via ldmatrix.x4.trans, B = weights (replicated over n),
//          12 HMMA, fp32 accum; lanes l&3==0 write 4 channels.
#define SMP_WSTRIDE 6720         // 6144 V + 384 off + 192 w
#define SMP_SMEM    (8 * SMP_WSTRIDE)

__global__ __launch_bounds__(256)
void sample_kernel(const float* __restrict__ refp, int warp0)
{
    extern __shared__ __align__(16) uint8_t ssm[];
    const int wslot = threadIdx.x >> 5;
    const int lane  = threadIdx.x & 31;
    const uint32_t wbase = smem_u32(ssm) + wslot * SMP_WSTRIDE;
    const uint32_t offb  = wbase + 6144;
    const uint32_t wwb   = wbase + 6528;

    const int warp = warp0 + blockIdx.x * 8 + wslot;
    const int h  = warp & 7;
    const int bq = warp >> 3;
    const int b  = bq >> 12;

    // ---- softmax over 24 logits ----
    float a = -INFINITY;
    if (lane < 24) a = g_qa[(size_t)bq * NQA + NOFF + h * 24 + lane];
    float m = a;
#pragma unroll
    for (int s = 16; s; s >>= 1) m = fmaxf(m, __shfl_xor_sync(0xffffffffu, m, s));
    float e = (lane < 24) ? __expf(a - m) : 0.f;
    float ssum = e;
#pragma unroll
    for (int s = 16; s; s >>= 1) ssum += __shfl_xor_sync(0xffffffffu, ssum, s);
    const float aw = e / ssum;

    if (lane < 24) {
        const int l = lane >> 2;
        const int p = lane & 3;
        const int H = c_H[l], W = c_W[l], S = c_S[l];
        const size_t ob = (size_t)bq * NQA + (((h * NLVL + l) * NPT + p) << 1);
        const float2 off2 = *(const float2*)(g_qa + ob);
        const size_t rb = ((size_t)bq * NLVL + l) << 1;
        const float rx = refp[rb + 0];
        const float ry = refp[rb + 1];
        const float x = rx * (float)W + off2.x - 0.5f;
        const float y = ry * (float)H + off2.y - 0.5f;
        const float xf = floorf(x), yf = floorf(y);
        const float lx = x - xf, ly = y - yf;
        const int ix = (int)xf, iy = (int)yf;
        const bool vx0 = (ix     >= 0) && (ix     < W);
        const bool vx1 = (ix + 1 >= 0) && (ix + 1 < W);
        const bool vy0 = (iy     >= 0) && (iy     < H);
        const bool vy1 = (iy + 1 >= 0) && (iy + 1 < H);
        const int cx0 = min(max(ix, 0), W - 1);
        const int cx1 = min(max(ix + 1, 0), W - 1);
        const int cy0 = min(max(iy, 0), H - 1);
        const int cy1 = min(max(iy + 1, 0), H - 1);
        const unsigned o00 = (unsigned)(S + cy0 * W + cx0) << 6;
        const unsigned o01 = (unsigned)(S + cy0 * W + cx1) << 6;
        const unsigned o10 = (unsigned)(S + cy1 * W + cx0) << 6;
        const unsigned o11 = (unsigned)(S + cy1 * W + cx1) << 6;
        const float w00 = aw * (1.f - lx) * (1.f - ly) * (float)(vx0 && vy0);
        const float w01 = aw * lx         * (1.f - ly) * (float)(vx1 && vy0);
        const float w10 = aw * (1.f - lx) * ly         * (float)(vx0 && vy1);
        const float w11 = aw * lx         * ly         * (float)(vx1 && vy1);
        // offsets: int4 at row group lane*4..lane*4+3
        asm volatile("st.shared.v4.b32 [%0], {%1,%2,%3,%4};"
                     :: "r"(offb + lane * 16),
                        "r"(o00), "r"(o01), "r"(o10), "r"(o11) : "memory");
        // weights bf16[96], row-major r = point*4 + corner
        asm volatile("st.shared.v2.b32 [%0], {%1,%2};"
                     :: "r"(wwb + lane * 8),
                        "r"(pack_bf16(w00, w01)), "r"(pack_bf16(w10, w11))
                     : "memory");
    }
    __syncwarp();

    // ---- gather: 96 rows x 64B via cp.async (L1-cached) ----
    const char* __restrict__ vbb =
        (const char*)g_vbf + (size_t)(b * NHEAD + h) * NVAL * (DHEAD * 2);
#pragma unroll
    for (int j = 0; j < 12; j++) {
        const int c = lane + 32 * j;
        const int row = c >> 2, cp = c & 3;
        uint32_t off;
        asm volatile("ld.shared.b32 %0, [%1];" : "=r"(off) : "r"(offb + row * 4));
        const uint32_t dst = wbase + row * 64 + ((cp ^ ((row >> 1) & 3)) << 4);
        cp16ca(dst, vbb + off + cp * 16);
    }
    CP_COMMIT();
    CP_WAIT(0);
    __syncwarp();

    // ---- MMA: D[32ch] = A(V^T 32x96) x B(w 96x8 replicated) ----
    float d[2][4] = {{0.f, 0.f, 0.f, 0.f}, {0.f, 0.f, 0.f, 0.f}};
    const int rowL = ((lane >> 4) & 1) * 8 + (lane & 7);   // k within 16-step
    const int chH  = (lane >> 3) & 1;                      // m-chunk half
#pragma unroll
    for (int ks = 0; ks < 6; ks++) {
        uint32_t bb[2];
        asm volatile("ld.shared.b32 %0, [%1];" : "=r"(bb[0])
                     : "r"(wwb + ks * 32 + (lane & 3) * 4));
        asm volatile("ld.shared.b32 %0, [%1];" : "=r"(bb[1])
                     : "r"(wwb + ks * 32 + (lane & 3) * 4 + 16));
        const int row = ks * 16 + rowL;
        const int xr  = (row >> 1) & 3;
#pragma unroll
        for (int mt = 0; mt < 2; mt++) {
            const uint32_t addr =
                wbase + row * 64 + (((mt * 2 + chH) ^ xr) << 4);
            uint32_t av[4];
            ldsm_x4t(av, addr);
            mma_bf16(d[mt], av, bb);
        }
    }

    // ---- epilogue: lanes with (lane&3)==0 hold n=0 column ----
    if ((lane & 3) == 0) {
        const int t = lane >> 2;
        __nv_bfloat16* dst = g_ms_h + (size_t)bq * CDIM + h * DHEAD;
        dst[t]      = __float2bfloat16_rn(d[0][0]);
        dst[t + 8]  = __float2bfloat16_rn(d[0][2]);
        dst[t + 16] = __float2bfloat16_rn(d[1][0]);
        dst[t + 24] = __float2bfloat16_rn(d[1][2]);
    }
}

// ---------------- launch: 4-slice 3-stream pipeline -------------------------
extern "C" void kernel_launch(void* const* d_in, const int* in_sizes, int n_in,
                              void* d_out, int out_size)
{
    const float* query  = (const float*)d_in[0];
    const float* qpos   = (const float*)d_in[1];
    const float* value  = (const float*)d_in[2];
    const float* refp   = (const float*)d_in[3];
    const float* W_off  = (const float*)d_in[5];
    const float* b_off  = (const float*)d_in[6];
    const float* W_attn = (const float*)d_in[7];
    const float* b_attn = (const float*)d_in[8];
    const float* W_val  = (const float*)d_in[9];
    const float* b_val  = (const float*)d_in[10];
    const float* W_out  = (const float*)d_in[11];
    const float* b_out  = (const float*)d_in[12];
    float* out = (float*)d_out;

    float *qa, *biasb;
    __nv_bfloat16 *vbf, *wth, *wtl, *valh, *qh, *ql, *msh;
    cudaGetSymbolAddress((void**)&vbf,   g_vbf);
    cudaGetSymbolAddress((void**)&qa,    g_qa);
    cudaGetSymbolAddress((void**)&biasb, g_bias);
    cudaGetSymbolAddress((void**)&wth,   g_Wt_hi);
    cudaGetSymbolAddress((void**)&wtl,   g_Wt_lo);
    cudaGetSymbolAddress((void**)&valh,  g_val_h);
    cudaGetSymbolAddress((void**)&qh,    g_q_h);
    cudaGetSymbolAddress((void**)&ql,    g_q_l);
    cudaGetSymbolAddress((void**)&msh,   g_ms_h);

    static cudaStream_t s2 = nullptr, s3 = nullptr;
    static cudaEvent_t evFork, evV[NSLC], evQ[NSLC], evS[NSLC];
    if (!s2) {
        cudaFuncSetAttribute(hgemm2_kernel<0>,
                             cudaFuncAttributeMaxDynamicSharedMemorySize, HG_SMEM);
        cudaFuncSetAttribute(hgemm2_kernel<1>,
                             cudaFuncAttributeMaxDynamicSharedMemorySize, HG_SMEM);
        cudaFuncSetAttribute(hgemm2_kernel<2>,
                             cudaFuncAttributeMaxDynamicSharedMemorySize, HG_SMEM);
        cudaFuncSetAttribute(sample_kernel,
                             cudaFuncAttributeMaxDynamicSharedMemorySize, SMP_SMEM);
        cudaStreamCreateWithFlags(&s2, cudaStreamNonBlocking);
        cudaStreamCreateWithFlags(&s3, cudaStreamNonBlocking);
        cudaEventCreateWithFlags(&evFork, cudaEventDisableTiming);
        for (int i = 0; i < NSLC; i++) {
            cudaEventCreateWithFlags(&evV[i], cudaEventDisableTiming);
            cudaEventCreateWithFlags(&evQ[i], cudaEventDisableTiming);
            cudaEventCreateWithFlags(&evS[i], cudaEventDisableTiming);
        }
    }

    // ---- fork ----
    cudaEventRecord(evFork, 0);
    cudaStreamWaitEvent(s2, evFork, 0);
    cudaStreamWaitEvent(s3, evFork, 0);

    // s2: value chain — W_val prep + value split + vproj slices
    prep_v_kernel<<<PV_NB, 256, 0, s2>>>(value, W_val, b_val);
    for (int i = 0; i < NSLC; i++) {
        hgemm2_kernel<2><<<dim3(MVS / 128, CDIM / 64), 256, HG_SMEM, s2>>>(
            valh, nullptr, wth, nullptr, biasb, nullptr, nullptr, vbf,
            i * MVS, CDIM, CDIM);
        cudaEventRecord(evV[i], s2);
    }

    // s0: query chain — other weights + q split + qa slices
    prep_qw_kernel<<<PQW_NB, 256>>>(W_off, b_off, W_attn, b_attn,
                                    W_out, b_out, query, qpos);
    for (int i = 0; i < NSLC; i++) {
        hgemm2_kernel<0><<<dim3(MQS / 128, NQA / 64), 256, HG_SMEM>>>(
            qh, ql, wth + 256 * CDIM, wtl + 256 * CDIM, biasb + 256,
            nullptr, qa, nullptr, i * MQS, NQA, CDIM);
        cudaEventRecord(evQ[i], 0);
    }

    // s3: sampler slices (slice i needs vproj_i + qa_i)
    for (int i = 0; i < NSLC; i++) {
        cudaStreamWaitEvent(s3, evQ[i], 0);
        cudaStreamWaitEvent(s3, evV[i], 0);
        sample_kernel<<<(MQS * NHEAD) / 8, 256, SMP_SMEM, s3>>>(
            refp, i * MQS * NHEAD);
        cudaEventRecord(evS[i], s3);
    }

    // s2: out GEMM slices (slice i needs sampler_i)
    for (int i = 0; i < NSLC; i++) {
        cudaStreamWaitEvent(s2, evS[i], 0);
        hgemm2_kernel<1><<<dim3(MQS / 128, CDIM / 64), 256, HG_SMEM, s2>>>(
            msh, nullptr, wth + 832 * CDIM, wtl + 832 * CDIM, biasb + 832,
            query, out, nullptr, i * MQS, CDIM, CDIM);
    }

    // join
    static cudaEvent_t evDone = nullptr;
    if (!evDone) cudaEventCreateWithFlags(&evDone, cudaEventDisableTiming);
    cudaEventRecord(evDone, s2);
    cudaStreamWaitEvent(0, evDone, 0);
}